// round 14
// baseline (speedup 1.0000x reference)
#include <cuda_runtime.h>
#include <cuda_bf16.h>
#include <cstdint>

#define B_   8
#define C_   256
#define N_   4096
#define M_   1024
#define HD_  64
#define EPSV 1e-5f

// ===================== helpers =====================
__device__ __forceinline__ uint32_t smem_u32(const void* p) {
    uint32_t a;
    asm("{ .reg .u64 tmp; cvta.to.shared.u64 tmp, %1; cvt.u32.u64 %0, tmp; }" : "=r"(a) : "l"(p));
    return a;
}
__device__ __forceinline__ void ldmx4(uint32_t r[4], uint32_t addr) {
    asm volatile("ldmatrix.sync.aligned.m8n8.x4.shared.b16 {%0,%1,%2,%3}, [%4];"
                 : "=r"(r[0]), "=r"(r[1]), "=r"(r[2]), "=r"(r[3]) : "r"(addr));
}
__device__ __forceinline__ void mma16816(float c[4], const uint32_t a[4], uint32_t b0, uint32_t b1) {
    asm volatile("mma.sync.aligned.m16n8k16.row.col.f32.bf16.bf16.f32 "
                 "{%0,%1,%2,%3}, {%4,%5,%6,%7}, {%8,%9}, {%0,%1,%2,%3};"
                 : "+f"(c[0]), "+f"(c[1]), "+f"(c[2]), "+f"(c[3])
                 : "r"(a[0]), "r"(a[1]), "r"(a[2]), "r"(a[3]), "r"(b0), "r"(b1));
}
__device__ __forceinline__ float ex2f(float x) {
    float r; asm("ex2.approx.ftz.f32 %0, %1;" : "=f"(r) : "f"(x)); return r;
}
__device__ __forceinline__ uint32_t pack_bf16x2(float lo, float hi) {
    uint32_t r;
    asm("cvt.rn.satfinite.bf16x2.f32 %0, %1, %2;" : "=r"(r) : "f"(hi), "f"(lo));
    return r;
}

// ===================== device scratch =====================
__device__ float g_part[B_ * 64 * 2];
__device__ float g_s[B_ * C_];
__device__ float g_t[B_ * C_];
__device__ __nv_bfloat16 g_xt [(size_t)B_ * N_ * C_];   // normalized, [b][n][c]
__device__ __nv_bfloat16 g_xds[(size_t)B_ * M_ * C_];   // pooled+norm, [b][m][c]
__device__ __nv_bfloat16 g_wqb[C_ * C_];                // wq has hd^-.5*log2e folded
__device__ __nv_bfloat16 g_wkb[HD_ * C_];
__device__ __nv_bfloat16 g_wvb[HD_ * C_];
__device__ __nv_bfloat16 g_wob[C_ * C_];
__device__ __nv_bfloat16 g_qt [(size_t)B_ * N_ * C_];   // Q, [b][n][c]
__device__ __nv_bfloat16 g_kt [B_ * M_ * HD_];          // K, [b][m][d]
__device__ __nv_bfloat16 g_vt [B_ * HD_ * M_];          // V, [b][d][m]
__device__ __nv_bfloat16 g_ao [(size_t)B_ * N_ * C_];   // attn out, [b][n][c]

// ===================== stats =====================
__global__ void reduce1(const float* __restrict__ x) {
    int b = blockIdx.y, chunk = blockIdx.x, t = threadIdx.x;
    const float4* p = (const float4*)(x + (size_t)b * C_ * N_ + (size_t)chunk * 16384);
    float s = 0.f, sq = 0.f;
#pragma unroll
    for (int i = 0; i < 16; i++) {
        float4 v = p[t + 256 * i];
        s  += v.x + v.y + v.z + v.w;
        sq += v.x * v.x + v.y * v.y + v.z * v.z + v.w * v.w;
    }
    __shared__ float ss[256], sq2[256];
    ss[t] = s; sq2[t] = sq;
    __syncthreads();
    for (int o = 128; o > 0; o >>= 1) {
        if (t < o) { ss[t] += ss[t + o]; sq2[t] += sq2[t + o]; }
        __syncthreads();
    }
    if (t == 0) {
        g_part[(b * 64 + chunk) * 2 + 0] = ss[0];
        g_part[(b * 64 + chunk) * 2 + 1] = sq2[0];
    }
}
__global__ void reduce2(const float* __restrict__ gn_w, const float* __restrict__ gn_b) {
    int b = blockIdx.x, t = threadIdx.x;
    __shared__ float ss[64], sq2[64];
    if (t < 64) { ss[t] = g_part[(b * 64 + t) * 2]; sq2[t] = g_part[(b * 64 + t) * 2 + 1]; }
    __syncthreads();
    for (int o = 32; o > 0; o >>= 1) {
        if (t < o) { ss[t] += ss[t + o]; sq2[t] += sq2[t + o]; }
        __syncthreads();
    }
    __shared__ float sh_mu, sh_inv;
    if (t == 0) {
        const float invN = 1.0f / (float)(C_ * N_);
        float mu  = ss[0] * invN;
        float var = sq2[0] * invN - mu * mu;
        sh_mu = mu; sh_inv = rsqrtf(var + EPSV);
    }
    __syncthreads();
    float sc = sh_inv * gn_w[t];
    g_s[b * C_ + t] = sc;
    g_t[b * C_ + t] = gn_b[t] - sh_mu * sc;
}

// ===================== prep: normalize + transpose to bf16 (float4 loads) =====
__global__ void prep_xt(const float* __restrict__ x) {
    __shared__ float sm[64 * 65];
    int b = blockIdx.z, c0 = blockIdx.y * 64, n0 = blockIdx.x * 64;
    int t = threadIdx.x;
#pragma unroll
    for (int i = 0; i < 4; i++) {
        int idx = t + 256 * i;
        int c = idx >> 4, ng = (idx & 15) * 4;
        int bc = b * C_ + c0 + c;
        float4 v = *(const float4*)&x[(size_t)bc * N_ + n0 + ng];
        float s = g_s[bc], tt = g_t[bc];
        sm[(ng + 0) * 65 + c] = fmaf(v.x, s, tt);
        sm[(ng + 1) * 65 + c] = fmaf(v.y, s, tt);
        sm[(ng + 2) * 65 + c] = fmaf(v.z, s, tt);
        sm[(ng + 3) * 65 + c] = fmaf(v.w, s, tt);
    }
    __syncthreads();
#pragma unroll
    for (int i = 0; i < 4; i++) {
        int idx = t + 256 * i;
        int cg = idx & 15, n = idx >> 4;
        const float* r = &sm[n * 65 + cg * 4];
        uint2 o;
        o.x = pack_bf16x2(r[0], r[1]);
        o.y = pack_bf16x2(r[2], r[3]);
        *(uint2*)(g_xt + ((size_t)(b * N_ + n0 + n)) * C_ + c0 + cg * 4) = o;
    }
}
// 2x2 avgpool reading g_xt (bf16), writes g_xds [b][m][c]
__global__ void pool_xt() {
    int t = threadIdx.x;
    int idx = blockIdx.x * 4 + (t >> 6);
    int b = idx >> 10, m = idx & 1023;
    int c4 = (t & 63) * 4;
    int nb = (m >> 5) * 128 + (m & 31) * 2;
    const __nv_bfloat16* base = g_xt + ((size_t)b * N_) * C_ + c4;
    float acc[4] = {0.f, 0.f, 0.f, 0.f};
    int offs[4] = {0, 1, 64, 65};
#pragma unroll
    for (int r = 0; r < 4; r++) {
        uint2 v = *(const uint2*)(base + (size_t)(nb + offs[r]) * C_);
        __nv_bfloat162 p0 = *(__nv_bfloat162*)&v.x;
        __nv_bfloat162 p1 = *(__nv_bfloat162*)&v.y;
        acc[0] += __bfloat162float(p0.x); acc[1] += __bfloat162float(p0.y);
        acc[2] += __bfloat162float(p1.x); acc[3] += __bfloat162float(p1.y);
    }
    uint2 o;
    o.x = pack_bf16x2(acc[0] * 0.25f, acc[1] * 0.25f);
    o.y = pack_bf16x2(acc[2] * 0.25f, acc[3] * 0.25f);
    *(uint2*)(g_xds + ((size_t)b * M_ + m) * C_ + c4) = o;
}
// all weight conversions in one launch (wq folds hd^-0.5 * log2e)
__global__ void cvt_all(const float* __restrict__ wq, const float* __restrict__ wk,
                        const float* __restrict__ wv, const float* __restrict__ wo) {
    const float QS = 0.125f * 1.4426950408889634f;
    int i = blockIdx.x * 256 + threadIdx.x;
    if (i < 65536)       g_wqb[i]          = __float2bfloat16(wq[i] * QS);
    else if (i < 81920)  g_wkb[i - 65536]  = __float2bfloat16(wk[i - 65536]);
    else if (i < 98304)  g_wvb[i - 81920]  = __float2bfloat16(wv[i - 81920]);
    else if (i < 163840) g_wob[i - 98304]  = __float2bfloat16(wo[i - 98304]);
}

// ===================== projection GEMM (R8: synchronous loads) =====================
// CTA: 128 rows x NT cols, K=256 in chunks of 32.
// mode 0: bf16 out[row][N]; mode 1: bf16 V transposed [d][M]; mode 2: fp32 residual out
template<int NT>
__global__ void __launch_bounds__(256) proj_mma(
    const __nv_bfloat16* __restrict__ A, const __nv_bfloat16* __restrict__ Bw,
    int rows, int N, int mode,
    __nv_bfloat16* __restrict__ outb, float* __restrict__ outf,
    const float* __restrict__ xres, const float* __restrict__ gamma)
{
    extern __shared__ char dsm[];
    __nv_bfloat16* As = (__nv_bfloat16*)dsm;              // [128][40]
    __nv_bfloat16* Bs = (__nv_bfloat16*)(dsm + 10240);    // [NT][40]
    float* Cs = (float*)dsm;                               // [NT][132] epilogue staging

    constexpr int NFR = NT / 16;
    int t = threadIdx.x, lane = t & 31, wid = t >> 5;
    int wm = wid & 3, wn = wid >> 2;
    int b = blockIdx.z, row0 = blockIdx.x * 128, n0 = blockIdx.y * NT;
    int g = lane >> 2, qt = lane & 3;

    float acc[2][NFR][4];
#pragma unroll
    for (int mi = 0; mi < 2; mi++)
#pragma unroll
        for (int ni = 0; ni < NFR; ni++)
#pragma unroll
            for (int e = 0; e < 4; e++) acc[mi][ni][e] = 0.f;

    const __nv_bfloat16* Ag = A + ((size_t)b * rows + row0) * 256;

    for (int k0 = 0; k0 < 256; k0 += 32) {
#pragma unroll
        for (int i = 0; i < 2; i++) {
            int idx = t + 256 * i;
            int r = idx >> 2, kc = (idx & 3) * 8;
            *(uint4*)(As + r * 40 + kc) = *(const uint4*)(Ag + (size_t)r * 256 + k0 + kc);
        }
#pragma unroll
        for (int i = 0; i < NT / 64; i++) {
            int idx = t + 256 * i;
            int r = idx >> 2, kc = (idx & 3) * 8;
            *(uint4*)(Bs + r * 40 + kc) = *(const uint4*)(Bw + (size_t)(n0 + r) * 256 + k0 + kc);
        }
        __syncthreads();
#pragma unroll
        for (int k16 = 0; k16 < 32; k16 += 16) {
            uint32_t af[2][4];
#pragma unroll
            for (int mi = 0; mi < 2; mi++) {
                uint32_t addr = smem_u32(As + (wm * 32 + mi * 16 + (lane & 15)) * 40
                                         + k16 + (lane >> 4) * 8);
                ldmx4(af[mi], addr);
            }
#pragma unroll
            for (int np = 0; np < NFR / 2; np++) {
                uint32_t bfm[4];
                uint32_t addr = smem_u32(Bs + (wn * (NT / 2) + np * 16 + (lane & 7) + ((lane >> 4) & 1) * 8) * 40
                                         + k16 + ((lane >> 3) & 1) * 8);
                ldmx4(bfm, addr);
                mma16816(acc[0][np * 2 + 0], af[0], bfm[0], bfm[1]);
                mma16816(acc[0][np * 2 + 1], af[0], bfm[2], bfm[3]);
                mma16816(acc[1][np * 2 + 0], af[1], bfm[0], bfm[1]);
                mma16816(acc[1][np * 2 + 1], af[1], bfm[2], bfm[3]);
            }
        }
        __syncthreads();
    }

    if (mode == 0) {
#pragma unroll
        for (int mi = 0; mi < 2; mi++)
#pragma unroll
            for (int ni = 0; ni < NFR; ni++) {
                int r = row0 + wm * 32 + mi * 16 + g;
                int col = n0 + wn * (NT / 2) + ni * 8 + 2 * qt;
                *(uint32_t*)(outb + ((size_t)b * rows + r) * N + col) =
                    pack_bf16x2(acc[mi][ni][0], acc[mi][ni][1]);
                *(uint32_t*)(outb + ((size_t)b * rows + r + 8) * N + col) =
                    pack_bf16x2(acc[mi][ni][2], acc[mi][ni][3]);
            }
    } else if (mode == 1) {
#pragma unroll
        for (int mi = 0; mi < 2; mi++)
#pragma unroll
            for (int ni = 0; ni < NFR; ni++) {
                int r = row0 + wm * 32 + mi * 16 + g;
                int col = n0 + wn * (NT / 2) + ni * 8 + 2 * qt;
                outb[((size_t)b * HD_ + col)     * M_ + r]     = __float2bfloat16(acc[mi][ni][0]);
                outb[((size_t)b * HD_ + col + 1) * M_ + r]     = __float2bfloat16(acc[mi][ni][1]);
                outb[((size_t)b * HD_ + col)     * M_ + r + 8] = __float2bfloat16(acc[mi][ni][2]);
                outb[((size_t)b * HD_ + col + 1) * M_ + r + 8] = __float2bfloat16(acc[mi][ni][3]);
            }
    } else {
#pragma unroll
        for (int mi = 0; mi < 2; mi++)
#pragma unroll
            for (int ni = 0; ni < NFR; ni++) {
                int rL = wm * 32 + mi * 16 + g;
                int cL = wn * (NT / 2) + ni * 8 + 2 * qt;
                Cs[cL * 132 + rL]           = acc[mi][ni][0];
                Cs[(cL + 1) * 132 + rL]     = acc[mi][ni][1];
                Cs[cL * 132 + rL + 8]       = acc[mi][ni][2];
                Cs[(cL + 1) * 132 + rL + 8] = acc[mi][ni][3];
            }
        __syncthreads();
#pragma unroll
        for (int i = 0; i < NT / 8; i++) {
            int idx = t + 256 * i;
            int col = idx >> 5, r4 = (idx & 31) * 4;
            float4 v = *(float4*)&Cs[col * 132 + r4];
            size_t off = ((size_t)b * C_ + n0 + col) * (size_t)N_ + row0 + r4;
            float gch = gamma[n0 + col];
            float4 xr = *(const float4*)&xres[off];
            v.x = fmaf(gch, v.x, xr.x);
            v.y = fmaf(gch, v.y, xr.y);
            v.z = fmaf(gch, v.z, xr.z);
            v.w = fmaf(gch, v.w, xr.w);
            *(float4*)&outf[off] = v;
        }
    }
}

// ========== attention (R8): 128 q/CTA, 8 warps, bf16 HMMA, synchronous loads ==========
__global__ void __launch_bounds__(256) attn_mma() {
    __shared__ __align__(16) __nv_bfloat16 Ks[64 * 72];   // [m][d] pad 72
    __shared__ __align__(16) __nv_bfloat16 Vs[64 * 72];   // [d][m] pad 72

    int t = threadIdx.x, lane = t & 31, w = t >> 5;
    int g = lane >> 2, qt = lane & 3;
    int bh = blockIdx.y, b = bh >> 2, h = bh & 3;
    int n0 = blockIdx.x * 128;

    uint32_t qf[4][4];
    const __nv_bfloat16* Qg = g_qt + ((size_t)b * N_ + n0 + w * 16) * C_ + h * HD_;
#pragma unroll
    for (int k16 = 0; k16 < 4; k16++) {
        qf[k16][0] = *(const uint32_t*)(Qg + (size_t)g * C_       + k16 * 16 + 2 * qt);
        qf[k16][1] = *(const uint32_t*)(Qg + (size_t)(g + 8) * C_ + k16 * 16 + 2 * qt);
        qf[k16][2] = *(const uint32_t*)(Qg + (size_t)g * C_       + k16 * 16 + 8 + 2 * qt);
        qf[k16][3] = *(const uint32_t*)(Qg + (size_t)(g + 8) * C_ + k16 * 16 + 8 + 2 * qt);
    }

    float oacc[8][4];
#pragma unroll
    for (int ni = 0; ni < 8; ni++)
#pragma unroll
        for (int e = 0; e < 4; e++) oacc[ni][e] = 0.f;
    float lsum0 = 0.f, lsum1 = 0.f;

    const __nv_bfloat16* Kg = g_kt + (size_t)b * M_ * HD_;
    const __nv_bfloat16* Vg = g_vt + (size_t)b * HD_ * M_;

    for (int m0 = 0; m0 < M_; m0 += 64) {
#pragma unroll
        for (int i = 0; i < 2; i++) {
            int idx = t + 256 * i;
            int r = idx >> 3, cc = (idx & 7) * 8;
            *(uint4*)(Ks + r * 72 + cc) = *(const uint4*)(Kg + (size_t)(m0 + r) * HD_ + cc);
            *(uint4*)(Vs + r * 72 + cc) = *(const uint4*)(Vg + (size_t)r * M_ + m0 + cc);
        }
        __syncthreads();

        float sacc[8][4];
#pragma unroll
        for (int ni = 0; ni < 8; ni++)
#pragma unroll
            for (int e = 0; e < 4; e++) sacc[ni][e] = 0.f;
#pragma unroll
        for (int k16 = 0; k16 < 4; k16++) {
#pragma unroll
            for (int np = 0; np < 4; np++) {
                uint32_t bfm[4];
                uint32_t addr = smem_u32(Ks + (np * 16 + (lane & 7) + ((lane >> 4) & 1) * 8) * 72
                                         + k16 * 16 + ((lane >> 3) & 1) * 8);
                ldmx4(bfm, addr);
                mma16816(sacc[np * 2 + 0], qf[k16], bfm[0], bfm[1]);
                mma16816(sacc[np * 2 + 1], qf[k16], bfm[2], bfm[3]);
            }
        }

        uint32_t pa[4][4];
#pragma unroll
        for (int j = 0; j < 4; j++) {
            float e00 = ex2f(sacc[2 * j][0]),     e01 = ex2f(sacc[2 * j][1]);
            float e10 = ex2f(sacc[2 * j][2]),     e11 = ex2f(sacc[2 * j][3]);
            float f00 = ex2f(sacc[2 * j + 1][0]), f01 = ex2f(sacc[2 * j + 1][1]);
            float f10 = ex2f(sacc[2 * j + 1][2]), f11 = ex2f(sacc[2 * j + 1][3]);
            lsum0 += e00 + e01 + f00 + f01;
            lsum1 += e10 + e11 + f10 + f11;
            pa[j][0] = pack_bf16x2(e00, e01);
            pa[j][1] = pack_bf16x2(e10, e11);
            pa[j][2] = pack_bf16x2(f00, f01);
            pa[j][3] = pack_bf16x2(f10, f11);
        }

#pragma unroll
        for (int k16 = 0; k16 < 4; k16++) {
#pragma unroll
            for (int np = 0; np < 4; np++) {
                uint32_t bfm[4];
                uint32_t addr = smem_u32(Vs + (np * 16 + (lane & 7) + ((lane >> 4) & 1) * 8) * 72
                                         + k16 * 16 + ((lane >> 3) & 1) * 8);
                ldmx4(bfm, addr);
                mma16816(oacc[np * 2 + 0], pa[k16], bfm[0], bfm[1]);
                mma16816(oacc[np * 2 + 1], pa[k16], bfm[2], bfm[3]);
            }
        }
        __syncthreads();
    }

#pragma unroll
    for (int o = 1; o <= 2; o <<= 1) {
        lsum0 += __shfl_xor_sync(0xffffffffu, lsum0, o);
        lsum1 += __shfl_xor_sync(0xffffffffu, lsum1, o);
    }
    float inv0 = 1.0f / lsum0, inv1 = 1.0f / lsum1;

    __nv_bfloat16* Og = g_ao + ((size_t)b * N_ + n0 + w * 16) * C_ + h * HD_;
#pragma unroll
    for (int ni = 0; ni < 8; ni++) {
        int col = ni * 8 + 2 * qt;
        *(uint32_t*)(Og + (size_t)g * C_ + col) =
            pack_bf16x2(oacc[ni][0] * inv0, oacc[ni][1] * inv0);
        *(uint32_t*)(Og + (size_t)(g + 8) * C_ + col) =
            pack_bf16x2(oacc[ni][2] * inv1, oacc[ni][3] * inv1);
    }
}

// ===================== launch (multi-stream fork/join, graph-capturable) ==========
extern "C" void kernel_launch(void* const* d_in, const int* in_sizes, int n_in,
                              void* d_out, int out_size) {
    const float* x    = (const float*)d_in[0];
    const float* gn_w = (const float*)d_in[1];
    const float* gn_b = (const float*)d_in[2];
    const float* wq   = (const float*)d_in[3];
    const float* wk   = (const float*)d_in[4];
    const float* wv   = (const float*)d_in[5];
    const float* wo   = (const float*)d_in[6];
    const float* gamma= (const float*)d_in[7];
    float* out = (float*)d_out;

    __nv_bfloat16 *pxt, *pxds, *pwq, *pwk, *pwv, *pwo, *pqt, *pkt, *pvt, *pao;
    cudaGetSymbolAddress((void**)&pxt,  g_xt);
    cudaGetSymbolAddress((void**)&pxds, g_xds);
    cudaGetSymbolAddress((void**)&pwq,  g_wqb);
    cudaGetSymbolAddress((void**)&pwk,  g_wkb);
    cudaGetSymbolAddress((void**)&pwv,  g_wvb);
    cudaGetSymbolAddress((void**)&pwo,  g_wob);
    cudaGetSymbolAddress((void**)&pqt,  g_qt);
    cudaGetSymbolAddress((void**)&pkt,  g_kt);
    cudaGetSymbolAddress((void**)&pvt,  g_vt);
    cudaGetSymbolAddress((void**)&pao,  g_ao);

    // one-time resources (identical work every call; created outside any capture path's
    // device-memory budget — streams/events hold no tracked device allocations)
    static cudaStream_t s2 = nullptr;
    static cudaEvent_t e_fork = nullptr, e_cvt = nullptr, e_prep = nullptr, e_kv = nullptr;
    if (!s2) {
        cudaStreamCreateWithFlags(&s2, cudaStreamNonBlocking);
        cudaEventCreateWithFlags(&e_fork, cudaEventDisableTiming);
        cudaEventCreateWithFlags(&e_cvt,  cudaEventDisableTiming);
        cudaEventCreateWithFlags(&e_prep, cudaEventDisableTiming);
        cudaEventCreateWithFlags(&e_kv,   cudaEventDisableTiming);
        cudaFuncSetAttribute(proj_mma<128>, cudaFuncAttributeMaxDynamicSharedMemorySize, 67584);
    }

    // fork: side stream joins the capture via event dependency
    cudaEventRecord(e_fork, 0);
    cudaStreamWaitEvent(s2, e_fork, 0);

    // side stream: weight conversion (independent of x-chain)
    cvt_all<<<640, 256, 0, s2>>>(wq, wk, wv, wo);
    cudaEventRecord(e_cvt, s2);

    // main stream: stats + normalize/transpose
    reduce1<<<dim3(64, 8), 256>>>(x);
    reduce2<<<8, 256>>>(gn_w, gn_b);
    prep_xt<<<dim3(64, 4, 8), 256>>>(x);
    cudaEventRecord(e_prep, 0);

    // side stream: pool + K/V projections (need prep_xt and cvt_all — both ordered)
    cudaStreamWaitEvent(s2, e_prep, 0);
    pool_xt<<<2048, 256, 0, s2>>>();
    proj_mma<64><<<dim3(8, 1, 8), 256, 15360, s2>>>(pxds, pwk, M_, 64, 0, pkt, nullptr, nullptr, nullptr);
    proj_mma<64><<<dim3(8, 1, 8), 256, 15360, s2>>>(pxds, pwv, M_, 64, 1, pvt, nullptr, nullptr, nullptr);
    cudaEventRecord(e_kv, s2);

    // main stream: Q projection (needs prep_xt [ordered on main] + cvt_all [event])
    cudaStreamWaitEvent(0, e_cvt, 0);
    proj_mma<128><<<dim3(32, 2, 8), 256, 20480>>>(pxt, pwq, N_, 256, 0, pqt, nullptr, nullptr, nullptr);

    // join: attention needs Q (main) + K/V (side)
    cudaStreamWaitEvent(0, e_kv, 0);
    attn_mma<<<dim3(32, 32), 256>>>();

    // out = x + gamma * (ao @ wo^T), channel-major fp32
    proj_mma<128><<<dim3(32, 2, 8), 256, 67584>>>(pao, pwo, N_, 256, 2, nullptr, out, x, gamma);
}

// round 16
// speedup vs baseline: 1.5008x; 1.5008x over previous
#include <cuda_runtime.h>
#include <cuda_bf16.h>
#include <cstdint>

#define B_   8
#define C_   256
#define N_   4096
#define M_   1024
#define HD_  64
#define EPSV 1e-5f

// ===================== helpers =====================
__device__ __forceinline__ uint32_t smem_u32(const void* p) {
    uint32_t a;
    asm("{ .reg .u64 tmp; cvta.to.shared.u64 tmp, %1; cvt.u32.u64 %0, tmp; }" : "=r"(a) : "l"(p));
    return a;
}
__device__ __forceinline__ void ldmx4(uint32_t r[4], uint32_t addr) {
    asm volatile("ldmatrix.sync.aligned.m8n8.x4.shared.b16 {%0,%1,%2,%3}, [%4];"
                 : "=r"(r[0]), "=r"(r[1]), "=r"(r[2]), "=r"(r[3]) : "r"(addr));
}
__device__ __forceinline__ void mma16816(float c[4], const uint32_t a[4], uint32_t b0, uint32_t b1) {
    asm volatile("mma.sync.aligned.m16n8k16.row.col.f32.bf16.bf16.f32 "
                 "{%0,%1,%2,%3}, {%4,%5,%6,%7}, {%8,%9}, {%0,%1,%2,%3};"
                 : "+f"(c[0]), "+f"(c[1]), "+f"(c[2]), "+f"(c[3])
                 : "r"(a[0]), "r"(a[1]), "r"(a[2]), "r"(a[3]), "r"(b0), "r"(b1));
}
__device__ __forceinline__ float ex2f(float x) {
    float r; asm("ex2.approx.ftz.f32 %0, %1;" : "=f"(r) : "f"(x)); return r;
}
__device__ __forceinline__ uint32_t pack_bf16x2(float lo, float hi) {
    uint32_t r;
    asm("cvt.rn.satfinite.bf16x2.f32 %0, %1, %2;" : "=r"(r) : "f"(hi), "f"(lo));
    return r;
}

// ===================== device scratch =====================
__device__ float g_part[B_ * 64 * 2];
__device__ float g_s[B_ * C_];
__device__ float g_t[B_ * C_];
__device__ __nv_bfloat16 g_xt [(size_t)B_ * N_ * C_];   // normalized, [b][n][c]
__device__ __nv_bfloat16 g_xds[(size_t)B_ * M_ * C_];   // pooled+norm, [b][m][c]
__device__ __nv_bfloat16 g_wqb[C_ * C_];                // wq has hd^-.5*log2e folded
__device__ __nv_bfloat16 g_wkb[HD_ * C_];
__device__ __nv_bfloat16 g_wvb[HD_ * C_];
__device__ __nv_bfloat16 g_wob[C_ * C_];
__device__ __nv_bfloat16 g_qt [(size_t)B_ * N_ * C_];   // Q, [b][n][c]
__device__ __nv_bfloat16 g_kt [B_ * M_ * HD_];          // K, [b][m][d]
__device__ __nv_bfloat16 g_vt [B_ * HD_ * M_];          // V, [b][d][m]
__device__ __nv_bfloat16 g_ao [(size_t)B_ * N_ * C_];   // attn out, [b][n][c]

// ===================== stats =====================
__global__ void reduce1(const float* __restrict__ x) {
    int b = blockIdx.y, chunk = blockIdx.x, t = threadIdx.x;
    const float4* p = (const float4*)(x + (size_t)b * C_ * N_ + (size_t)chunk * 16384);
    float s = 0.f, sq = 0.f;
#pragma unroll
    for (int i = 0; i < 16; i++) {
        float4 v = p[t + 256 * i];
        s  += v.x + v.y + v.z + v.w;
        sq += v.x * v.x + v.y * v.y + v.z * v.z + v.w * v.w;
    }
    __shared__ float ss[256], sq2[256];
    ss[t] = s; sq2[t] = sq;
    __syncthreads();
    for (int o = 128; o > 0; o >>= 1) {
        if (t < o) { ss[t] += ss[t + o]; sq2[t] += sq2[t + o]; }
        __syncthreads();
    }
    if (t == 0) {
        g_part[(b * 64 + chunk) * 2 + 0] = ss[0];
        g_part[(b * 64 + chunk) * 2 + 1] = sq2[0];
    }
}
__global__ void reduce2(const float* __restrict__ gn_w, const float* __restrict__ gn_b) {
    int b = blockIdx.x, t = threadIdx.x;
    __shared__ float ss[64], sq2[64];
    if (t < 64) { ss[t] = g_part[(b * 64 + t) * 2]; sq2[t] = g_part[(b * 64 + t) * 2 + 1]; }
    __syncthreads();
    for (int o = 32; o > 0; o >>= 1) {
        if (t < o) { ss[t] += ss[t + o]; sq2[t] += sq2[t + o]; }
        __syncthreads();
    }
    __shared__ float sh_mu, sh_inv;
    if (t == 0) {
        const float invN = 1.0f / (float)(C_ * N_);
        float mu  = ss[0] * invN;
        float var = sq2[0] * invN - mu * mu;
        sh_mu = mu; sh_inv = rsqrtf(var + EPSV);
    }
    __syncthreads();
    float sc = sh_inv * gn_w[t];
    g_s[b * C_ + t] = sc;
    g_t[b * C_ + t] = gn_b[t] - sh_mu * sc;
}

// ========== fused prep: normalize + transpose to bf16 xt AND 2x2 pooled xds ==========
// CTA: 64 channels x 128 n (two spatial rows) -> xt tile + 32 pooled m-rows.
__global__ void __launch_bounds__(256) prep_fused(const float* __restrict__ x) {
    __shared__ float sm[128 * 65];
    int b = blockIdx.z, c0 = blockIdx.y * 64, hp = blockIdx.x;   // hp: h-row pair 0..31
    int n0 = hp * 128;
    int t = threadIdx.x;
    // load 64c x 128n floats, normalize, store [n][c] in smem
#pragma unroll
    for (int i = 0; i < 8; i++) {
        int idx = t + 256 * i;
        int c = idx >> 5, ng = (idx & 31) * 4;
        int bc = b * C_ + c0 + c;
        float4 v = *(const float4*)&x[(size_t)bc * N_ + n0 + ng];
        float s = g_s[bc], tt = g_t[bc];
        sm[(ng + 0) * 65 + c] = fmaf(v.x, s, tt);
        sm[(ng + 1) * 65 + c] = fmaf(v.y, s, tt);
        sm[(ng + 2) * 65 + c] = fmaf(v.z, s, tt);
        sm[(ng + 3) * 65 + c] = fmaf(v.w, s, tt);
    }
    __syncthreads();
    // transposed bf16 store of xt
#pragma unroll
    for (int i = 0; i < 8; i++) {
        int idx = t + 256 * i;
        int cg = idx & 15, n = idx >> 4;
        const float* r = &sm[n * 65 + cg * 4];
        uint2 o;
        o.x = pack_bf16x2(r[0], r[1]);
        o.y = pack_bf16x2(r[2], r[3]);
        *(uint2*)(g_xt + ((size_t)(b * N_ + n0 + n)) * C_ + c0 + cg * 4) = o;
    }
    // pooled output: 32 m-rows (mw 0..31) x 64 c, from fp32 normalized values
#pragma unroll
    for (int i = 0; i < 8; i++) {
        int idx = t + 256 * i;
        int mw = idx >> 6, c = idx & 63;         // mw 0..31 from (idx: 2048 total)
        int w2 = mw * 2;
        float v = 0.25f * (sm[w2 * 65 + c] + sm[(w2 + 1) * 65 + c]
                         + sm[(64 + w2) * 65 + c] + sm[(64 + w2 + 1) * 65 + c]);
        int m = hp * 32 + mw;
        g_xds[((size_t)(b * M_ + m)) * C_ + c0 + c] = __float2bfloat16(v);
    }
}
// all weight conversions in one launch (wq folds hd^-0.5 * log2e)
__global__ void cvt_all(const float* __restrict__ wq, const float* __restrict__ wk,
                        const float* __restrict__ wv, const float* __restrict__ wo) {
    const float QS = 0.125f * 1.4426950408889634f;
    int i = blockIdx.x * 256 + threadIdx.x;
    if (i < 65536)       g_wqb[i]          = __float2bfloat16(wq[i] * QS);
    else if (i < 81920)  g_wkb[i - 65536]  = __float2bfloat16(wk[i - 65536]);
    else if (i < 98304)  g_wvb[i - 81920]  = __float2bfloat16(wv[i - 81920]);
    else if (i < 163840) g_wob[i - 98304]  = __float2bfloat16(wo[i - 98304]);
}

// ===================== projection GEMM (R8: synchronous loads) =====================
// CTA: 128 rows x NT cols, K=256 in chunks of 32.
// mode 0: bf16 out[row][N]; mode 2: fp32 channel-major residual out
template<int NT>
__global__ void __launch_bounds__(256) proj_mma(
    const __nv_bfloat16* __restrict__ A, const __nv_bfloat16* __restrict__ Bw,
    int rows, int N, int mode,
    __nv_bfloat16* __restrict__ outb, float* __restrict__ outf,
    const float* __restrict__ xres, const float* __restrict__ gamma)
{
    extern __shared__ char dsm[];
    __nv_bfloat16* As = (__nv_bfloat16*)dsm;              // [128][40]
    __nv_bfloat16* Bs = (__nv_bfloat16*)(dsm + 10240);    // [NT][40]
    float* Cs = (float*)dsm;                               // [NT][132] epilogue staging

    constexpr int NFR = NT / 16;
    int t = threadIdx.x, lane = t & 31, wid = t >> 5;
    int wm = wid & 3, wn = wid >> 2;
    int b = blockIdx.z, row0 = blockIdx.x * 128, n0 = blockIdx.y * NT;
    int g = lane >> 2, qt = lane & 3;

    float acc[2][NFR][4];
#pragma unroll
    for (int mi = 0; mi < 2; mi++)
#pragma unroll
        for (int ni = 0; ni < NFR; ni++)
#pragma unroll
            for (int e = 0; e < 4; e++) acc[mi][ni][e] = 0.f;

    const __nv_bfloat16* Ag = A + ((size_t)b * rows + row0) * 256;

    for (int k0 = 0; k0 < 256; k0 += 32) {
#pragma unroll
        for (int i = 0; i < 2; i++) {
            int idx = t + 256 * i;
            int r = idx >> 2, kc = (idx & 3) * 8;
            *(uint4*)(As + r * 40 + kc) = *(const uint4*)(Ag + (size_t)r * 256 + k0 + kc);
        }
#pragma unroll
        for (int i = 0; i < NT / 64; i++) {
            int idx = t + 256 * i;
            int r = idx >> 2, kc = (idx & 3) * 8;
            *(uint4*)(Bs + r * 40 + kc) = *(const uint4*)(Bw + (size_t)(n0 + r) * 256 + k0 + kc);
        }
        __syncthreads();
#pragma unroll
        for (int k16 = 0; k16 < 32; k16 += 16) {
            uint32_t af[2][4];
#pragma unroll
            for (int mi = 0; mi < 2; mi++) {
                uint32_t addr = smem_u32(As + (wm * 32 + mi * 16 + (lane & 15)) * 40
                                         + k16 + (lane >> 4) * 8);
                ldmx4(af[mi], addr);
            }
#pragma unroll
            for (int np = 0; np < NFR / 2; np++) {
                uint32_t bfm[4];
                uint32_t addr = smem_u32(Bs + (wn * (NT / 2) + np * 16 + (lane & 7) + ((lane >> 4) & 1) * 8) * 40
                                         + k16 + ((lane >> 3) & 1) * 8);
                ldmx4(bfm, addr);
                mma16816(acc[0][np * 2 + 0], af[0], bfm[0], bfm[1]);
                mma16816(acc[0][np * 2 + 1], af[0], bfm[2], bfm[3]);
                mma16816(acc[1][np * 2 + 0], af[1], bfm[0], bfm[1]);
                mma16816(acc[1][np * 2 + 1], af[1], bfm[2], bfm[3]);
            }
        }
        __syncthreads();
    }

    if (mode == 0) {
#pragma unroll
        for (int mi = 0; mi < 2; mi++)
#pragma unroll
            for (int ni = 0; ni < NFR; ni++) {
                int r = row0 + wm * 32 + mi * 16 + g;
                int col = n0 + wn * (NT / 2) + ni * 8 + 2 * qt;
                *(uint32_t*)(outb + ((size_t)b * rows + r) * N + col) =
                    pack_bf16x2(acc[mi][ni][0], acc[mi][ni][1]);
                *(uint32_t*)(outb + ((size_t)b * rows + r + 8) * N + col) =
                    pack_bf16x2(acc[mi][ni][2], acc[mi][ni][3]);
            }
    } else {
#pragma unroll
        for (int mi = 0; mi < 2; mi++)
#pragma unroll
            for (int ni = 0; ni < NFR; ni++) {
                int rL = wm * 32 + mi * 16 + g;
                int cL = wn * (NT / 2) + ni * 8 + 2 * qt;
                Cs[cL * 132 + rL]           = acc[mi][ni][0];
                Cs[(cL + 1) * 132 + rL]     = acc[mi][ni][1];
                Cs[cL * 132 + rL + 8]       = acc[mi][ni][2];
                Cs[(cL + 1) * 132 + rL + 8] = acc[mi][ni][3];
            }
        __syncthreads();
#pragma unroll
        for (int i = 0; i < NT / 8; i++) {
            int idx = t + 256 * i;
            int col = idx >> 5, r4 = (idx & 31) * 4;
            float4 v = *(float4*)&Cs[col * 132 + r4];
            size_t off = ((size_t)b * C_ + n0 + col) * (size_t)N_ + row0 + r4;
            float gch = gamma[n0 + col];
            float4 xr = *(const float4*)&xres[off];
            v.x = fmaf(gch, v.x, xr.x);
            v.y = fmaf(gch, v.y, xr.y);
            v.z = fmaf(gch, v.z, xr.z);
            v.w = fmaf(gch, v.w, xr.w);
            *(float4*)&outf[off] = v;
        }
    }
}

// ======== merged K+V projection: blockIdx.y selects K (row-major) or V (transposed) ====
__global__ void __launch_bounds__(256) kv_mma() {
    __shared__ __align__(16) __nv_bfloat16 As[128 * 40];
    __shared__ __align__(16) __nv_bfloat16 Bs[64 * 40];

    int t = threadIdx.x, lane = t & 31, wid = t >> 5;
    int wm = wid & 3, wn = wid >> 2;
    int b = blockIdx.z, row0 = blockIdx.x * 128;
    int isV = blockIdx.y;
    int g = lane >> 2, qt = lane & 3;

    const __nv_bfloat16* Bw = isV ? g_wvb : g_wkb;

    float acc[2][4][4];
#pragma unroll
    for (int mi = 0; mi < 2; mi++)
#pragma unroll
        for (int ni = 0; ni < 4; ni++)
#pragma unroll
            for (int e = 0; e < 4; e++) acc[mi][ni][e] = 0.f;

    const __nv_bfloat16* Ag = g_xds + ((size_t)b * M_ + row0) * 256;

    for (int k0 = 0; k0 < 256; k0 += 32) {
#pragma unroll
        for (int i = 0; i < 2; i++) {
            int idx = t + 256 * i;
            int r = idx >> 2, kc = (idx & 3) * 8;
            *(uint4*)(As + r * 40 + kc) = *(const uint4*)(Ag + (size_t)r * 256 + k0 + kc);
        }
        {
            int r = t >> 2, kc = (t & 3) * 8;
            *(uint4*)(Bs + r * 40 + kc) = *(const uint4*)(Bw + (size_t)r * 256 + k0 + kc);
        }
        __syncthreads();
#pragma unroll
        for (int k16 = 0; k16 < 32; k16 += 16) {
            uint32_t af[2][4];
#pragma unroll
            for (int mi = 0; mi < 2; mi++) {
                uint32_t addr = smem_u32(As + (wm * 32 + mi * 16 + (lane & 15)) * 40
                                         + k16 + (lane >> 4) * 8);
                ldmx4(af[mi], addr);
            }
#pragma unroll
            for (int np = 0; np < 2; np++) {
                uint32_t bfm[4];
                uint32_t addr = smem_u32(Bs + (wn * 32 + np * 16 + (lane & 7) + ((lane >> 4) & 1) * 8) * 40
                                         + k16 + ((lane >> 3) & 1) * 8);
                ldmx4(bfm, addr);
                mma16816(acc[0][np * 2 + 0], af[0], bfm[0], bfm[1]);
                mma16816(acc[0][np * 2 + 1], af[0], bfm[2], bfm[3]);
                mma16816(acc[1][np * 2 + 0], af[1], bfm[0], bfm[1]);
                mma16816(acc[1][np * 2 + 1], af[1], bfm[2], bfm[3]);
            }
        }
        __syncthreads();
    }

    if (!isV) {
#pragma unroll
        for (int mi = 0; mi < 2; mi++)
#pragma unroll
            for (int ni = 0; ni < 4; ni++) {
                int r = row0 + wm * 32 + mi * 16 + g;
                int col = wn * 32 + ni * 8 + 2 * qt;
                *(uint32_t*)(g_kt + ((size_t)b * M_ + r) * HD_ + col) =
                    pack_bf16x2(acc[mi][ni][0], acc[mi][ni][1]);
                *(uint32_t*)(g_kt + ((size_t)b * M_ + r + 8) * HD_ + col) =
                    pack_bf16x2(acc[mi][ni][2], acc[mi][ni][3]);
            }
    } else {
#pragma unroll
        for (int mi = 0; mi < 2; mi++)
#pragma unroll
            for (int ni = 0; ni < 4; ni++) {
                int r = row0 + wm * 32 + mi * 16 + g;
                int col = wn * 32 + ni * 8 + 2 * qt;
                g_vt[((size_t)b * HD_ + col)     * M_ + r]     = __float2bfloat16(acc[mi][ni][0]);
                g_vt[((size_t)b * HD_ + col + 1) * M_ + r]     = __float2bfloat16(acc[mi][ni][1]);
                g_vt[((size_t)b * HD_ + col)     * M_ + r + 8] = __float2bfloat16(acc[mi][ni][2]);
                g_vt[((size_t)b * HD_ + col + 1) * M_ + r + 8] = __float2bfloat16(acc[mi][ni][3]);
            }
    }
}

// ========== attention (R8): 128 q/CTA, 8 warps, bf16 HMMA, synchronous loads ==========
__global__ void __launch_bounds__(256) attn_mma() {
    __shared__ __align__(16) __nv_bfloat16 Ks[64 * 72];   // [m][d] pad 72
    __shared__ __align__(16) __nv_bfloat16 Vs[64 * 72];   // [d][m] pad 72

    int t = threadIdx.x, lane = t & 31, w = t >> 5;
    int g = lane >> 2, qt = lane & 3;
    int bh = blockIdx.y, b = bh >> 2, h = bh & 3;
    int n0 = blockIdx.x * 128;

    uint32_t qf[4][4];
    const __nv_bfloat16* Qg = g_qt + ((size_t)b * N_ + n0 + w * 16) * C_ + h * HD_;
#pragma unroll
    for (int k16 = 0; k16 < 4; k16++) {
        qf[k16][0] = *(const uint32_t*)(Qg + (size_t)g * C_       + k16 * 16 + 2 * qt);
        qf[k16][1] = *(const uint32_t*)(Qg + (size_t)(g + 8) * C_ + k16 * 16 + 2 * qt);
        qf[k16][2] = *(const uint32_t*)(Qg + (size_t)g * C_       + k16 * 16 + 8 + 2 * qt);
        qf[k16][3] = *(const uint32_t*)(Qg + (size_t)(g + 8) * C_ + k16 * 16 + 8 + 2 * qt);
    }

    float oacc[8][4];
#pragma unroll
    for (int ni = 0; ni < 8; ni++)
#pragma unroll
        for (int e = 0; e < 4; e++) oacc[ni][e] = 0.f;
    float lsum0 = 0.f, lsum1 = 0.f;

    const __nv_bfloat16* Kg = g_kt + (size_t)b * M_ * HD_;
    const __nv_bfloat16* Vg = g_vt + (size_t)b * HD_ * M_;

    for (int m0 = 0; m0 < M_; m0 += 64) {
#pragma unroll
        for (int i = 0; i < 2; i++) {
            int idx = t + 256 * i;
            int r = idx >> 3, cc = (idx & 7) * 8;
            *(uint4*)(Ks + r * 72 + cc) = *(const uint4*)(Kg + (size_t)(m0 + r) * HD_ + cc);
            *(uint4*)(Vs + r * 72 + cc) = *(const uint4*)(Vg + (size_t)r * M_ + m0 + cc);
        }
        __syncthreads();

        float sacc[8][4];
#pragma unroll
        for (int ni = 0; ni < 8; ni++)
#pragma unroll
            for (int e = 0; e < 4; e++) sacc[ni][e] = 0.f;
#pragma unroll
        for (int k16 = 0; k16 < 4; k16++) {
#pragma unroll
            for (int np = 0; np < 4; np++) {
                uint32_t bfm[4];
                uint32_t addr = smem_u32(Ks + (np * 16 + (lane & 7) + ((lane >> 4) & 1) * 8) * 72
                                         + k16 * 16 + ((lane >> 3) & 1) * 8);
                ldmx4(bfm, addr);
                mma16816(sacc[np * 2 + 0], qf[k16], bfm[0], bfm[1]);
                mma16816(sacc[np * 2 + 1], qf[k16], bfm[2], bfm[3]);
            }
        }

        uint32_t pa[4][4];
#pragma unroll
        for (int j = 0; j < 4; j++) {
            float e00 = ex2f(sacc[2 * j][0]),     e01 = ex2f(sacc[2 * j][1]);
            float e10 = ex2f(sacc[2 * j][2]),     e11 = ex2f(sacc[2 * j][3]);
            float f00 = ex2f(sacc[2 * j + 1][0]), f01 = ex2f(sacc[2 * j + 1][1]);
            float f10 = ex2f(sacc[2 * j + 1][2]), f11 = ex2f(sacc[2 * j + 1][3]);
            lsum0 += e00 + e01 + f00 + f01;
            lsum1 += e10 + e11 + f10 + f11;
            pa[j][0] = pack_bf16x2(e00, e01);
            pa[j][1] = pack_bf16x2(e10, e11);
            pa[j][2] = pack_bf16x2(f00, f01);
            pa[j][3] = pack_bf16x2(f10, f11);
        }

#pragma unroll
        for (int k16 = 0; k16 < 4; k16++) {
#pragma unroll
            for (int np = 0; np < 4; np++) {
                uint32_t bfm[4];
                uint32_t addr = smem_u32(Vs + (np * 16 + (lane & 7) + ((lane >> 4) & 1) * 8) * 72
                                         + k16 * 16 + ((lane >> 3) & 1) * 8);
                ldmx4(bfm, addr);
                mma16816(oacc[np * 2 + 0], pa[k16], bfm[0], bfm[1]);
                mma16816(oacc[np * 2 + 1], pa[k16], bfm[2], bfm[3]);
            }
        }
        __syncthreads();
    }

#pragma unroll
    for (int o = 1; o <= 2; o <<= 1) {
        lsum0 += __shfl_xor_sync(0xffffffffu, lsum0, o);
        lsum1 += __shfl_xor_sync(0xffffffffu, lsum1, o);
    }
    float inv0 = 1.0f / lsum0, inv1 = 1.0f / lsum1;

    __nv_bfloat16* Og = g_ao + ((size_t)b * N_ + n0 + w * 16) * C_ + h * HD_;
#pragma unroll
    for (int ni = 0; ni < 8; ni++) {
        int col = ni * 8 + 2 * qt;
        *(uint32_t*)(Og + (size_t)g * C_ + col) =
            pack_bf16x2(oacc[ni][0] * inv0, oacc[ni][1] * inv0);
        *(uint32_t*)(Og + (size_t)(g + 8) * C_ + col) =
            pack_bf16x2(oacc[ni][2] * inv1, oacc[ni][3] * inv1);
    }
}

// ===================== launch (single stream) =====================
extern "C" void kernel_launch(void* const* d_in, const int* in_sizes, int n_in,
                              void* d_out, int out_size) {
    const float* x    = (const float*)d_in[0];
    const float* gn_w = (const float*)d_in[1];
    const float* gn_b = (const float*)d_in[2];
    const float* wq   = (const float*)d_in[3];
    const float* wk   = (const float*)d_in[4];
    const float* wv   = (const float*)d_in[5];
    const float* wo   = (const float*)d_in[6];
    const float* gamma= (const float*)d_in[7];
    float* out = (float*)d_out;

    __nv_bfloat16 *pxt, *pwq, *pwo, *pqt, *pao;
    cudaGetSymbolAddress((void**)&pxt,  g_xt);
    cudaGetSymbolAddress((void**)&pwq,  g_wqb);
    cudaGetSymbolAddress((void**)&pwo,  g_wob);
    cudaGetSymbolAddress((void**)&pqt,  g_qt);
    cudaGetSymbolAddress((void**)&pao,  g_ao);

    cudaFuncSetAttribute(proj_mma<128>, cudaFuncAttributeMaxDynamicSharedMemorySize, 67584);

    cvt_all<<<640, 256>>>(wq, wk, wv, wo);
    reduce1<<<dim3(64, 8), 256>>>(x);
    reduce2<<<8, 256>>>(gn_w, gn_b);
    prep_fused<<<dim3(32, 4, 8), 256>>>(x);

    // Q = xt @ wq^T -> bf16 [b][n][256]
    proj_mma<128><<<dim3(32, 2, 8), 256, 20480>>>(pxt, pwq, N_, 256, 0, pqt, nullptr, nullptr, nullptr);
    // K + V in one launch (y: 0=K row-major, 1=V transposed)
    kv_mma<<<dim3(8, 2, 8), 256>>>();

    attn_mma<<<dim3(32, 32), 256>>>();

    // out = x + gamma * (ao @ wo^T), channel-major fp32
    proj_mma<128><<<dim3(32, 2, 8), 256, 67584>>>(pao, pwo, N_, 256, 2, nullptr, out, x, gamma);
}